// round 2
// baseline (speedup 1.0000x reference)
#include <cuda_runtime.h>

// Clifford product in Cl(3,0), basis order: 1, e1, e2, e3, e12, e13, e23, e123.
// out[n,k] = sum_{i,j} a[n,i] b[n,j] S[i,j,k], S hardcoded (Cayley table, e_k^2=+1).
//
// Pure streaming: 96 B/multivector, 402 MB total. R1 measured 6.62 TB/s (83.6%).
// R2: 2 multivectors/thread (8 front-batched LDG.128 -> deeper MLP) + streaming
// cache hints (__ldcs/__stcs) to stop polluting L2 with zero-reuse lines.

__device__ __forceinline__ void clifford8(const float4 alo, const float4 ahi,
                                          const float4 blo, const float4 bhi,
                                          float4& clo, float4& chi) {
    const float a0 = alo.x, a1 = alo.y, a2 = alo.z, a3 = alo.w;
    const float a4 = ahi.x, a5 = ahi.y, a6 = ahi.z, a7 = ahi.w;
    const float b0 = blo.x, b1 = blo.y, b2 = blo.z, b3 = blo.w;
    const float b4 = bhi.x, b5 = bhi.y, b6 = bhi.z, b7 = bhi.w;

    clo.x = a0*b0 + a1*b1 + a2*b2 + a3*b3 - a4*b4 - a5*b5 - a6*b6 - a7*b7;
    clo.y = a0*b1 + a1*b0 - a2*b4 - a3*b5 + a4*b2 + a5*b3 - a6*b7 - a7*b6;
    clo.z = a0*b2 + a1*b4 + a2*b0 - a3*b6 - a4*b1 + a5*b7 + a6*b3 + a7*b5;
    clo.w = a0*b3 + a1*b5 + a2*b6 + a3*b0 - a4*b7 - a5*b1 - a6*b2 - a7*b4;
    chi.x = a0*b4 + a1*b2 - a2*b1 + a3*b7 + a4*b0 - a5*b6 + a6*b5 + a7*b3;
    chi.y = a0*b5 + a1*b3 - a2*b7 - a3*b1 + a4*b6 + a5*b0 - a6*b4 - a7*b2;
    chi.z = a0*b6 + a1*b7 + a2*b3 - a3*b2 - a4*b5 + a5*b4 + a6*b0 + a7*b1;
    chi.w = a0*b7 + a1*b6 - a2*b5 + a3*b4 + a4*b3 - a5*b2 + a6*b1 + a7*b0;
}

__global__ void __launch_bounds__(256)
CliffordProduct_85452669321821_kernel(const float4* __restrict__ a,
                                      const float4* __restrict__ b,
                                      float4* __restrict__ out,
                                      int n, int half) {
    const int e0 = blockIdx.x * blockDim.x + threadIdx.x;
    if (e0 >= half) return;
    const int e1 = e0 + half;

    // Front-batch all 8 loads (evict-first: zero reuse, don't pollute L2)
    const float4 alo0 = __ldcs(a + 2 * e0);
    const float4 ahi0 = __ldcs(a + 2 * e0 + 1);
    const float4 blo0 = __ldcs(b + 2 * e0);
    const float4 bhi0 = __ldcs(b + 2 * e0 + 1);
    const bool do1 = (e1 < n);
    const int e1c = do1 ? e1 : e0;  // clamp to keep loads in-bounds
    const float4 alo1 = __ldcs(a + 2 * e1c);
    const float4 ahi1 = __ldcs(a + 2 * e1c + 1);
    const float4 blo1 = __ldcs(b + 2 * e1c);
    const float4 bhi1 = __ldcs(b + 2 * e1c + 1);

    float4 clo, chi;
    clifford8(alo0, ahi0, blo0, bhi0, clo, chi);
    __stcs(out + 2 * e0, clo);
    __stcs(out + 2 * e0 + 1, chi);

    if (do1) {
        clifford8(alo1, ahi1, blo1, bhi1, clo, chi);
        __stcs(out + 2 * e1, clo);
        __stcs(out + 2 * e1 + 1, chi);
    }
}

extern "C" void kernel_launch(void* const* d_in, const int* in_sizes, int n_in,
                              void* d_out, int out_size) {
    const float4* a = (const float4*)d_in[0];
    const float4* b = (const float4*)d_in[1];
    float4* out = (float4*)d_out;

    const int n = in_sizes[0] / 8;     // number of multivectors
    const int half = (n + 1) / 2;      // elements handled per "first slot"
    const int threads = 256;
    const int blocks = (half + threads - 1) / threads;
    CliffordProduct_85452669321821_kernel<<<blocks, threads>>>(a, b, out, n, half);
}